// round 11
// baseline (speedup 1.0000x reference)
#include <cuda_runtime.h>

#define B_  32
#define C_  64
#define H_  128
#define W_  128
#define HW  16384
#define CR  38               // floor(0.6*64)=38, even
#define CIR 26

// conv tile: 64 wide x 16 high, 256 threads = 64 tx x 4 ty, 4 rows/thread
#define CTW 64
#define CTH 16
#define HALO_W 70            // 64+6
#define HALO_H 22            // 16+6

// Scratch (allocation-free rule: __device__ globals)
__device__ unsigned long long g_mask[B_];
__device__ float4 g_maps[B_ * HW];   // {ravg, rmax, iravg, irmax}, 8 MB
__device__ float  g_A1  [B_ * HW];   // 2 MB
__device__ float  g_A2  [B_ * HW];   // 2 MB

// ---------------------------------------------------------------------------
// top-k(CR) rank mask for batch b; 64 threads cooperate.
// jax top_k tiebreak: smaller index wins ties.
// ---------------------------------------------------------------------------
__device__ __forceinline__ unsigned long long
compute_mask64(const float* __restrict__ M, int b, int t,
               float* sm, unsigned long long* smask) {
    if (t == 0) *smask = 0ull;
    sm[t] = __ldg(M + b * C_ + t);
    __syncthreads();
    float v = sm[t];
    int rank = 0;
    #pragma unroll
    for (int j = 0; j < C_; j++) {
        float mj = sm[j];
        rank += (mj > v) || (mj == v && j < t);
    }
    if (rank < CR) atomicOr(smask, 1ull << t);
    __syncthreads();
    return *smask;
}

// ---------------------------------------------------------------------------
// Kernel 1: mask + channel reductions. 2048 CTAs x 64 threads, thread = one
// float4 pixel-group x 64 channels (warp-wide 512 B contiguous per channel).
// Explicit 8-deep load batches for MLP. Default caching policy ON PURPOSE:
// the x bytes left in L2 are harvested by the reversed combine kernel.
// Masked-out entries are exact zeros in the reference -> max init to 0.
// ---------------------------------------------------------------------------
__global__ void __launch_bounds__(64) reduce_kernel(
        const float* __restrict__ x, const float* __restrict__ M) {
    __shared__ float sm[C_];
    __shared__ unsigned long long smask;

    int t     = threadIdx.x;                // 0..63
    int b     = blockIdx.x >> 6;            // 64 CTAs per batch
    int slice = blockIdx.x & 63;
    int group = slice * 64 + t;             // float4 pixel-group 0..4095

    unsigned long long mask = compute_mask64(M, b, t, sm, &smask);
    if (slice == 0 && t == 0) g_mask[b] = mask;

    const float4* xb = (const float4*)(x + (size_t)b * C_ * HW) + group;

    float4 rs = {0,0,0,0}, rm = {0,0,0,0};
    float4 is = {0,0,0,0}, im = {0,0,0,0};

    #pragma unroll
    for (int cb = 0; cb < C_; cb += 8) {
        float4 v[8];
        #pragma unroll
        for (int j = 0; j < 8; j++)
            v[j] = __ldg(xb + (cb + j) * (HW / 4));
        #pragma unroll
        for (int j = 0; j < 8; j++) {
            if ((mask >> (cb + j)) & 1ull) {
                rs.x += v[j].x; rs.y += v[j].y; rs.z += v[j].z; rs.w += v[j].w;
                rm.x = fmaxf(rm.x, v[j].x); rm.y = fmaxf(rm.y, v[j].y);
                rm.z = fmaxf(rm.z, v[j].z); rm.w = fmaxf(rm.w, v[j].w);
            } else {
                is.x += v[j].x; is.y += v[j].y; is.z += v[j].z; is.w += v[j].w;
                im.x = fmaxf(im.x, v[j].x); im.y = fmaxf(im.y, v[j].y);
                im.z = fmaxf(im.z, v[j].z); im.w = fmaxf(im.w, v[j].w);
            }
        }
    }

    const float kr = 1.0f / (float)CR, ki = 1.0f / (float)CIR;
    float4* mp = g_maps + (size_t)b * HW + group * 4;
    mp[0] = make_float4(rs.x * kr, rm.x, is.x * ki, im.x);
    mp[1] = make_float4(rs.y * kr, rm.y, is.y * ki, im.y);
    mp[2] = make_float4(rs.z * kr, rm.z, is.z * ki, im.z);
    mp[3] = make_float4(rs.w * kr, rm.w, is.w * ki, im.w);
}

// ---------------------------------------------------------------------------
// Kernel 2: 7x7 conv (2ch->1, zero-pad 3) + BN + relu + sigmoid -> A1, A2.
// CTA = 64x16 tile. Thread = col tx, rows ty*4..ty*4+3. Per kw: one 10-tall
// vertical register segment (conflict-free contiguous LDS.128 across lanes),
// reused over all 7 kh and 4 output rows -> 70 LDS.128 per 4 pixels.
// ---------------------------------------------------------------------------
__global__ void __launch_bounds__(256) conv_kernel(
        const float* __restrict__ cw,
        const float* __restrict__ gamma,
        const float* __restrict__ beta,
        const float* __restrict__ mean,
        const float* __restrict__ var) {
    __shared__ float4 smaps[HALO_H][HALO_W];    // 24.6 KB
    __shared__ float sw[98];

    int t  = threadIdx.x;
    int b  = blockIdx.x >> 4;               // 16 tiles per batch
    int ti = blockIdx.x & 15;
    int h0 = (ti >> 1) * CTH;               // 8 tile-rows
    int w0 = (ti & 1) * CTW;                // 2 tile-cols

    if (t < 98) sw[t] = __ldg(cw + t);

    const float4* mb = g_maps + (size_t)b * HW;
    for (int i = t; i < HALO_H * HALO_W; i += 256) {
        int r  = i / HALO_W;
        int cx = i - r * HALO_W;
        int gh = h0 + r - 3;
        int gw = w0 + cx - 3;
        float4 v = {0,0,0,0};
        if (gh >= 0 && gh < H_ && gw >= 0 && gw < W_)
            v = __ldg(mb + gh * W_ + gw);
        smaps[r][cx] = v;
    }
    __syncthreads();

    int tx = t & 63;                        // 0..63  (lane-consecutive cols)
    int ty = t >> 6;                        // 0..3   (4-row group)
    int r0 = ty * 4;                        // first local output row

    float y1[4] = {0,0,0,0}, y2[4] = {0,0,0,0};

    #pragma unroll
    for (int kw = 0; kw < 7; kw++) {
        float4 seg[10];
        #pragma unroll
        for (int s = 0; s < 10; s++)
            seg[s] = smaps[r0 + s][tx + kw];
        #pragma unroll
        for (int kh = 0; kh < 7; kh++) {
            float w0c = sw[kh * 7 + kw];
            float w1c = sw[49 + kh * 7 + kw];
            #pragma unroll
            for (int j = 0; j < 4; j++) {
                float4 m = seg[j + kh];
                y1[j] = fmaf(m.x, w0c, fmaf(m.y, w1c, y1[j]));
                y2[j] = fmaf(m.z, w0c, fmaf(m.w, w1c, y2[j]));
            }
        }
    }

    float scale = rsqrtf(__ldg(var) + 1e-5f) * __ldg(gamma);
    float bias  = __ldg(beta) - __ldg(mean) * scale;

    #pragma unroll
    for (int j = 0; j < 4; j++) {
        float v1 = fmaxf(fmaf(y1[j], scale, bias), 0.f);
        float v2 = fmaxf(fmaf(y2[j], scale, bias), 0.f);
        int p = b * HW + (h0 + r0 + j) * W_ + (w0 + tx);
        g_A1[p] = 1.0f / (1.0f + expf(-v1));
        g_A2[p] = 1.0f / (1.0f + expf(-v2));
    }
}

// ---------------------------------------------------------------------------
// Kernel 3: out = x * (relevant-channel ? A_S1 : A_S2), float4-vectorized.
// REVERSED CTA order: consume x MRU-first so the L2 residual left by the
// reduce kernel (ascending stream) is harvested as hits. out stores are
// evict-first (__stcs) to protect the residual; x loads default policy.
// ---------------------------------------------------------------------------
__global__ void combine_kernel(const float* __restrict__ x,
                               float* __restrict__ out) {
    // reverse at CTA granularity, keep within-CTA ascending for coalescing
    size_t i = (size_t)(gridDim.x - 1 - blockIdx.x) * blockDim.x + threadIdx.x;
    size_t e = i << 2;                                         // element index
    int b    = (int)(e >> 20);          // C_*HW = 2^20
    int c    = (int)((e >> 14) & 63);
    int pix4 = (int)((e & (HW - 1)) >> 2);

    float4 v = ((const float4*)x)[i];

    bool rel = (g_mask[b] >> c) & 1ull;
    const float4* A4 = (const float4*)(rel ? g_A1 : g_A2);
    float4 a = __ldg(A4 + ((size_t)b * HW >> 2) + pix4);

    float4 r;
    r.x = v.x * a.x;
    r.y = v.y * a.y;
    r.z = v.z * a.z;
    r.w = v.w * a.w;
    __stcs((float4*)out + i, r);
}

// ---------------------------------------------------------------------------
extern "C" void kernel_launch(void* const* d_in, const int* in_sizes, int n_in,
                              void* d_out, int out_size) {
    const float* x     = (const float*)d_in[0];
    const float* M     = (const float*)d_in[1];
    const float* cw    = (const float*)d_in[2];
    const float* gamma = (const float*)d_in[3];
    const float* beta  = (const float*)d_in[4];
    const float* mean  = (const float*)d_in[5];
    const float* var   = (const float*)d_in[6];
    float* out = (float*)d_out;

    reduce_kernel<<<B_ * 64, 64>>>(x, M);                         // 2048 CTAs
    conv_kernel  <<<B_ * 16, 256>>>(cw, gamma, beta, mean, var);  // 512 CTAs

    const int NV4 = (B_ * C_ * HW) / 4;                  // 8388608
    combine_kernel<<<NV4 / 256, 256>>>(x, out);          // 32768 CTAs
}